// round 10
// baseline (speedup 1.0000x reference)
#include <cuda_runtime.h>
#include <math.h>

#define H 256
#define W 832
#define B 2
#define HW (H*W)
#define INFV 1e9f
#define NT 256
#define PXB 1024          // pixels per block (HW = 208*1024 exactly)
#define MAXPTS 192        // smem point-list cap (mean ~8, edges<=~40 per 1024px)

// Packed fixed-point accumulator per pixel (cleared by graph memset node each
// replay; integer atomics -> bit-deterministic).
//   bits[ 0,22): sum round(w*2^12)            (den)
//   bits[22,43): sum round(w*(dy+4)*2^12)     (ny, weight-proportional bias)
//   bits[43,64): sum round(w*(dx+8)*2^11)     (nx, weight-proportional bias)
// Sparsify guarantees kept points pairwise Chebyshev dist >= 3 -> <= 49
// contributions per pixel -> field maxima 0.2M/1.4M/1.5M -> no carries.
__device__ ulonglong2 g_pack[(B*HW)/2];

// circular 3x3 box blur at (i,j)  (matches sum of jnp.roll wraps)
__device__ __forceinline__ float blur_at(const float* __restrict__ m, int i, int j) {
    float s = 0.f;
    #pragma unroll
    for (int di = -1; di <= 1; di++) {
        int ii = i + di; ii = (ii < 0) ? ii + H : (ii >= H ? ii - H : ii);
        #pragma unroll
        for (int dj = -1; dj <= 1; dj++) {
            int jj = j + dj; jj = (jj < 0) ? jj + W : (jj >= W ? jj - W : jj);
            s += m[ii*W + jj];
        }
    }
    return s;
}

// orientation = atan2(gy,gx) of blurred map, jnp.gradient border rules
__device__ __forceinline__ float theta_at(const float* __restrict__ m, int i, int j) {
    float gy, gx;
    if (i == 0)        gy = blur_at(m, 1, j)   - blur_at(m, 0, j);
    else if (i == H-1) gy = blur_at(m, H-1, j) - blur_at(m, H-2, j);
    else               gy = 0.5f * (blur_at(m, i+1, j) - blur_at(m, i-1, j));
    if (j == 0)        gx = blur_at(m, i, 1)   - blur_at(m, i, 0);
    else if (j == W-1) gx = blur_at(m, i, W-1) - blur_at(m, i, W-2);
    else               gx = 0.5f * (blur_at(m, i, j+1) - blur_at(m, i, j-1));
    return atan2f(gy, gx);
}

// ---- Kernel 1: fused sparsify + block-local point list + search + scatter ----
// Block = 1024 consecutive pixels of one batch. Kept points go to an smem
// list; the block's 8 warps then take one point each (parallel, no global
// queue, no cross-warp serialization).
__global__ void __launch_bounds__(NT)
fusedK(const float* __restrict__ src, const float* __restrict__ dst,
       const int* __restrict__ xx,  const int* __restrict__ yy,  int K,
       const int* __restrict__ cxx, const int* __restrict__ cyy, int C) {
    __shared__ float s_wk[512];   // sense weights exp(-r/5)
    __shared__ int   s_cco[512];  // packed (oy<<16)|(ox&0xffff)
    __shared__ int   s_kco[128];  // search offsets packed
    __shared__ float s_kd[128];   // search distances
    __shared__ int   s_cnt;
    __shared__ int2  s_pts[MAXPTS];   // {in-batch flat pos, theta bits}

    int tid = threadIdx.x;
    if (tid == 0) s_cnt = 0;
    for (int k = tid; k < C; k += NT) {
        int ox = cxx[k], oy = cyy[k];
        s_wk[k]  = expf(-sqrtf((float)(ox*ox + oy*oy)) / 5.0f);
        s_cco[k] = (oy << 16) | (ox & 0xffff);
    }
    for (int k = tid; k < K; k += NT) {
        int ox = xx[k], oy = yy[k];
        s_kco[k] = (oy << 16) | (ox & 0xffff);
        s_kd[k]  = sqrtf((float)(ox*ox + oy*oy));
    }
    __syncthreads();

    // ---- compact phase: 4 pixels per thread ----
    int base = blockIdx.x * PXB;            // HW % PXB == 0 -> single batch
    int b    = base / HW;
    const float* s = src + b*HW;
    const float* d = dst + b*HW;
    int p0 = (base % HW) + tid*4;
    float4 v = *(const float4*)(s + p0);    // coalesced; W % 4 == 0 -> same row

    bool e[4] = {v.x > 0.5f, v.y > 0.5f, v.z > 0.5f, v.w > 0.5f};
    if (e[0] | e[1] | e[2] | e[3]) {        // ~8% of threads
        int i = p0 / W, j0 = p0 % W;
        #pragma unroll
        for (int c = 0; c < 4; c++) {
            if (!e[c]) continue;
            int j = j0 + c;
            // kept iff no edge with smaller linear index in the 5x5 window:
            // rows i-2,i-1 (all 5 cols) + row i (2 cols left). Rows below never.
            bool viol = false;
            #pragma unroll
            for (int r = -2; r <= -1; r++) {
                int row = i + r;
                if (row < 0) continue;
                const float* rp = s + row*W;
                #pragma unroll
                for (int dx = -2; dx <= 2; dx++) {
                    int jj = j + dx;
                    if (jj >= 0 && jj < W && rp[jj] > 0.5f) viol = true;
                }
            }
            #pragma unroll
            for (int dx = -2; dx <= -1; dx++) {
                int jj = j + dx;
                if (jj >= 0 && s[i*W + jj] > 0.5f) viol = true;
            }
            if (!viol) {
                float ts = theta_at(s, i, j);
                int slot = atomicAdd(&s_cnt, 1);
                if (slot < MAXPTS)
                    s_pts[slot] = make_int2(i*W + j, __float_as_int(ts));
            }
        }
    }
    __syncthreads();

    // ---- point phase: one warp per kept point ----
    int n = s_cnt; if (n > MAXPTS) n = MAXPTS;
    int wid  = tid >> 5;
    int lane = tid & 31;
    unsigned long long* pk = (unsigned long long*)g_pack + b*HW;

    for (int pt = wid; pt < n; pt += NT/32) {
        int2 rec = s_pts[pt];                // lane-uniform smem read
        int p = rec.x;
        int i = p / W, j = p % W;
        float ts = __int_as_float(rec.y);

        // search split across lanes (per-lane k strictly increasing)
        float best = INFV; int bestk = K;
        for (int k = lane; k < K; k += 32) {
            int co = s_kco[k];
            int ox = (int)(short)(co & 0xffff), oy = co >> 16;
            int ii = i + oy, jj = j + ox;
            if (ii >= 0 && ii < H && jj >= 0 && jj < W && d[ii*W + jj] > 0.5f) {
                float td = theta_at(d, ii, jj);
                float sc = 20.0f * s_kd[k] + 10.5f * (1.0f - cosf(ts - td));
                if (sc < best) { best = sc; bestk = k; }
            }
        }
        #pragma unroll
        for (int off = 16; off; off >>= 1) {   // argmin, first-index tie-break
            float s2 = __shfl_xor_sync(0xffffffffu, best,  off);
            int   k2 = __shfl_xor_sync(0xffffffffu, bestk, off);
            if (s2 < best || (s2 == best && k2 < bestk)) { best = s2; bestk = k2; }
        }
        if (best >= 0.5f * INFV) continue;

        int cow = s_kco[bestk];                // uniform broadcast read
        float bdx8 = (float)((int)(short)(cow & 0xffff) + 8);   // dx+8 in [1,15]
        float bdy4 = (float)((cow >> 16) + 4);                  // dy+4 in [1,7]

        // warp-parallel scatter over the sense window (symmetric offsets)
        for (int k = lane; k < C; k += 32) {
            int co = s_cco[k];
            int ox = (int)(short)(co & 0xffff), oy = co >> 16;
            int ii = i + oy, jj = j + ox;
            if (ii >= 0 && ii < H && jj >= 0 && jj < W) {
                float w = s_wk[k];
                unsigned fx = (unsigned)(int)rintf(w * bdx8 * 2048.0f);
                unsigned fy = (unsigned)(int)rintf(w * bdy4 * 4096.0f);
                unsigned fw = (unsigned)(int)rintf(w * 4096.0f);
                unsigned long long add =
                    ((unsigned long long)fx << 43) |
                    ((unsigned long long)fy << 22) |
                    (unsigned long long)fw;
                atomicAdd(&pk[ii*W + jj], add);   // no return use -> REDG
            }
        }
    }
}

// ---- Kernel 2: decode fixed-point (4 pixels/thread, 2 independent 16B loads) ----
__global__ void __launch_bounds__(NT)
finalB(float* __restrict__ out) {
    int t = blockIdx.x * NT + threadIdx.x;     // one thread = 4 consecutive pixels
    if (t >= (B*HW)/4) return;
    ulonglong2 va = g_pack[2*t];               // cleared by next replay's memset node
    ulonglong2 vb = g_pack[2*t + 1];

    int p0 = t * 4;
    int b  = p0 / HW;
    int p  = p0 % HW;
    int i  = p / W;                            // W % 4 == 0 -> all 4 same row
    int j0 = p % W;
    float fi = (float)i;

    unsigned long long vs[4] = {va.x, va.y, vb.x, vb.y};
    float ox[4], oy[4];
    #pragma unroll
    for (int c = 0; c < 4; c++) {
        unsigned long long v = vs[c];
        float den = (float)(int)(v & 0x3FFFFFULL)          * (1.0f/4096.0f);
        float sy  = (float)(int)((v >> 22) & 0x1FFFFFULL)  * (1.0f/4096.0f);
        float sx  = (float)(int)(v >> 43)                  * (1.0f/2048.0f);
        float nx  = sx - 8.0f * den;
        float ny  = sy - 4.0f * den;
        float inv = 1.0f / (den + 1e-6f);
        ox[c] = (float)(j0 + c) + 0.6f * nx * inv;
        oy[c] = fi              + 0.6f * ny * inv;
    }
    *(float4*)(out + b*2*HW + p)      = make_float4(ox[0], ox[1], ox[2], ox[3]);
    *(float4*)(out + b*2*HW + HW + p) = make_float4(oy[0], oy[1], oy[2], oy[3]);
}

extern "C" void kernel_launch(void* const* d_in, const int* in_sizes, int n_in,
                              void* d_out, int out_size) {
    const float* src = (const float*)d_in[0];
    const float* dst = (const float*)d_in[1];
    const int* xx  = (const int*)d_in[2];
    const int* yy  = (const int*)d_in[3];
    const int* cxx = (const int*)d_in[6];
    const int* cyy = (const int*)d_in[7];
    int K = in_sizes[2];   // 105 search offsets
    int C = in_sizes[6];   // 441 sense offsets
    float* out = (float*)d_out;

    void* pack_p = nullptr;
    cudaGetSymbolAddress(&pack_p, g_pack);
    cudaMemsetAsync(pack_p, 0, sizeof(g_pack));

    fusedK<<<(B*HW)/PXB, NT>>>(src, dst, xx, yy, K, cxx, cyy, C);
    finalB<<<(B*HW)/(NT*4), NT>>>(out);
}

// round 11
// speedup vs baseline: 1.3099x; 1.3099x over previous
#include <cuda_runtime.h>
#include <math.h>

#define H 256
#define W 832
#define B 2
#define HW (H*W)
#define INFV 1e9f
#define NT 256
#define CAP 32768

// Packed fixed-point accumulator per pixel (cleared by compactK each replay;
// integer atomics -> bit-deterministic).
//   bits[ 0,22): sum w12                      (den,  w12 = round(w*2^12))
//   bits[22,43): sum w12*(dy+4)               (ny, weight-proportional bias)
//   bits[43,64): sum w11*(dx+8)               (nx,  w11 = round(w*2^11))
// Sparsify guarantees kept points pairwise Chebyshev dist >= 3 -> <= 49
// contributions per pixel -> field maxima 1.5M/1.4M/0.2M -> no carries.
__device__ ulonglong2 g_pack[(B*HW)/2];
__device__ int g_cnt;           // kept-point count (reset by finalB for next replay)
__device__ int g_kept[CAP];     // flat positions b*HW + p

// circular 3x3 box blur at (i,j)  (matches sum of jnp.roll wraps)
__device__ __forceinline__ float blur_at(const float* __restrict__ m, int i, int j) {
    float s = 0.f;
    #pragma unroll
    for (int di = -1; di <= 1; di++) {
        int ii = i + di; ii = (ii < 0) ? ii + H : (ii >= H ? ii - H : ii);
        #pragma unroll
        for (int dj = -1; dj <= 1; dj++) {
            int jj = j + dj; jj = (jj < 0) ? jj + W : (jj >= W ? jj - W : jj);
            s += m[ii*W + jj];
        }
    }
    return s;
}

// orientation = atan2(gy,gx) of blurred map, jnp.gradient border rules
__device__ __forceinline__ float theta_at(const float* __restrict__ m, int i, int j) {
    float gy, gx;
    if (i == 0)        gy = blur_at(m, 1, j)   - blur_at(m, 0, j);
    else if (i == H-1) gy = blur_at(m, H-1, j) - blur_at(m, H-2, j);
    else               gy = 0.5f * (blur_at(m, i+1, j) - blur_at(m, i-1, j));
    if (j == 0)        gx = blur_at(m, i, 1)   - blur_at(m, i, 0);
    else if (j == W-1) gx = blur_at(m, i, W-1) - blur_at(m, i, W-2);
    else               gx = 0.5f * (blur_at(m, i, j+1) - blur_at(m, i, j-1));
    return atan2f(gy, gx);
}

// ---- Kernel 1: bitmap sparsify + compact kept points; also clears g_pack ----
// (identical to the R8 version: one warp = one 64-pixel row segment)
__global__ void __launch_bounds__(NT)
compactK(const float* __restrict__ src) {
    int gw   = (blockIdx.x * NT + threadIdx.x) >> 5;
    int lane = threadIdx.x & 31;
    int base = gw * 64;
    int b     = base / HW;
    int pbase = base % HW;
    const float* s = src + b*HW;

    g_pack[base/2 + lane] = make_ulonglong2(0ULL, 0ULL);

    float2 v = *(const float2*)(s + pbase + 2*lane);
    bool e0 = v.x > 0.5f, e1 = v.y > 0.5f;
    unsigned eb = __ballot_sync(0xffffffffu, e0 | e1);
    if (!eb) return;

    int i  = pbase / W;
    int jb = pbase % W;

    unsigned long long lowm[3]; unsigned him[3];
    #pragma unroll
    for (int r = 0; r < 3; r++) {
        int row = i - 2 + r;
        bool rv = (row >= 0);
        const float* rp = s + row*W;
        int cA = jb - 2 + lane;
        float vA = (rv && cA >= 0 && cA < W) ? rp[cA] : 0.f;
        unsigned mA = __ballot_sync(0xffffffffu, vA > 0.5f);
        int cB = jb + 30 + lane;
        float vB = (rv && cB < W) ? rp[cB] : 0.f;
        unsigned mB = __ballot_sync(0xffffffffu, vB > 0.5f);
        int cC = jb + 62 + lane;
        float vC = (rv && lane < 4 && cC < W) ? rp[cC] : 0.f;
        unsigned mC = __ballot_sync(0xffffffffu, vC > 0.5f) & 0xFu;
        lowm[r] = (unsigned long long)mA | ((unsigned long long)mB << 32);
        him[r]  = mC;
    }
    unsigned long long up_low = lowm[0] | lowm[1];
    unsigned up_hi = him[0] | him[1];

    auto win = [](unsigned long long low, unsigned hi, int t, unsigned m) -> unsigned {
        unsigned long long x = low >> t;
        if (t) x |= (unsigned long long)hi << (64 - t);
        return (unsigned)x & m;
    };
    int t0 = 2*lane, t1 = 2*lane + 1;
    bool viol0 = (win(up_low, up_hi, t0, 0x1Fu) | win(lowm[2], him[2], t0, 0x3u)) != 0u;
    bool viol1 = (win(up_low, up_hi, t1, 0x1Fu) | win(lowm[2], him[2], t1, 0x3u)) != 0u;
    bool keep0 = e0 && !viol0;
    bool keep1 = e1 && !viol1;

    unsigned kb0 = __ballot_sync(0xffffffffu, keep0);
    unsigned kb1 = __ballot_sync(0xffffffffu, keep1);
    int tot = __popc(kb0) + __popc(kb1);
    if (!tot) return;
    int s0 = 0;
    if (lane == 0) s0 = atomicAdd(&g_cnt, tot);
    s0 = __shfl_sync(0xffffffffu, s0, 0);
    unsigned below = (1u << lane) - 1u;
    if (keep0) {
        int slot = s0 + __popc(kb0 & below);
        if (slot < CAP) g_kept[slot] = base + t0;
    }
    if (keep1) {
        int slot = s0 + __popc(kb0) + __popc(kb1 & below);
        if (slot < CAP) g_kept[slot] = base + t1;
    }
}

// ---- Kernel 2: one warp per kept point: search + coalesced integer scatter ----
__global__ void __launch_bounds__(NT)
searchScatterK(const float* __restrict__ src, const float* __restrict__ dst,
               const int* __restrict__ xx,  const int* __restrict__ yy,  int K,
               int C) {
    __shared__ int4  s_tap[448];  // row-major taps: {ox, oy, w11, w12}
    __shared__ int   s_kco[128];  // search offsets packed (oy<<16)|(ox&0xffff)
    __shared__ float s_kd[128];   // search distances

    int tid = threadIdx.x;
    // Build row-major 21x21 tap table analytically (accumulation commutes, so
    // tap order is free; row-major makes warp scatter lanes hit consecutive
    // addresses -> coalesced REDG).
    for (int k = tid; k < C; k += NT) {
        int oy = k / 21 - 10;
        int ox = k % 21 - 10;
        float w = expf(-sqrtf((float)(ox*ox + oy*oy)) / 5.0f);
        s_tap[k] = make_int4(ox, oy, (int)rintf(w * 2048.0f), (int)rintf(w * 4096.0f));
    }
    for (int k = tid; k < K; k += NT) {
        int ox = xx[k], oy = yy[k];
        s_kco[k] = (oy << 16) | (ox & 0xffff);
        s_kd[k]  = sqrtf((float)(ox*ox + oy*oy));
    }
    __syncthreads();

    int gw    = (blockIdx.x * NT + tid) >> 5;
    int lane  = tid & 31;
    int nWarp = (gridDim.x * NT) >> 5;
    int n = g_cnt; if (n > CAP) n = CAP;

    for (int pt = gw; pt < n; pt += nWarp) {
        int pos = g_kept[pt];
        int b = pos / HW, p = pos % HW;
        int i = p / W,   p_j = p % W;
        int j = p_j;
        const float* s = src + b*HW;
        const float* d = dst + b*HW;

        float ts = 0.f;
        if (lane == 0) ts = theta_at(s, i, j);
        ts = __shfl_sync(0xffffffffu, ts, 0);

        // search split across lanes (per-lane k strictly increasing; input
        // offset order preserved -> first-min == reference argmin)
        float best = INFV; int bestk = K;
        for (int k = lane; k < K; k += 32) {
            int co = s_kco[k];
            int ox = (int)(short)(co & 0xffff), oy = co >> 16;
            int ii = i + oy, jj = j + ox;
            if (ii >= 0 && ii < H && jj >= 0 && jj < W && d[ii*W + jj] > 0.5f) {
                float td = theta_at(d, ii, jj);
                float sc = 20.0f * s_kd[k] + 10.5f * (1.0f - cosf(ts - td));
                if (sc < best) { best = sc; bestk = k; }
            }
        }
        #pragma unroll
        for (int off = 16; off; off >>= 1) {   // argmin, first-index tie-break
            float s2 = __shfl_xor_sync(0xffffffffu, best,  off);
            int   k2 = __shfl_xor_sync(0xffffffffu, bestk, off);
            if (s2 < best || (s2 == best && k2 < bestk)) { best = s2; bestk = k2; }
        }
        if (best >= 0.5f * INFV) continue;

        int cow = s_kco[bestk];                // uniform broadcast read
        int idx8 = (int)(short)(cow & 0xffff) + 8;   // dx+8 in [1,15]
        int idy4 = (cow >> 16) + 4;                  // dy+4 in [1,7]

        // warp-parallel scatter (symmetric offsets: scatter == gather)
        unsigned long long* pk = (unsigned long long*)g_pack + b*HW;
        if (i >= 10 && i < H-10 && j >= 10 && j < W-10) {
            // interior: no bounds checks; lanes hit consecutive addresses
            for (int k = lane; k < C; k += 32) {
                int4 tp = s_tap[k];
                unsigned long long add =
                    ((unsigned long long)(unsigned)(tp.z * idx8) << 43) |
                    ((unsigned long long)(unsigned)(tp.w * idy4) << 22) |
                    (unsigned long long)(unsigned)tp.w;
                atomicAdd(&pk[(i + tp.y)*W + (j + tp.x)], add);
            }
        } else {
            for (int k = lane; k < C; k += 32) {
                int4 tp = s_tap[k];
                int ii = i + tp.y, jj = j + tp.x;
                if (ii >= 0 && ii < H && jj >= 0 && jj < W) {
                    unsigned long long add =
                        ((unsigned long long)(unsigned)(tp.z * idx8) << 43) |
                        ((unsigned long long)(unsigned)(tp.w * idy4) << 22) |
                        (unsigned long long)(unsigned)tp.w;
                    atomicAdd(&pk[ii*W + jj], add);
                }
            }
        }
    }
}

// ---- Kernel 3: decode fixed-point (4 pixels/thread, 2 independent 16B loads) ----
__global__ void __launch_bounds__(NT)
finalB(float* __restrict__ out) {
    int t = blockIdx.x * NT + threadIdx.x;     // one thread = 4 consecutive pixels
    if (t >= (B*HW)/4) return;
    ulonglong2 va = g_pack[2*t];               // cleared by next replay's compactK
    ulonglong2 vb = g_pack[2*t + 1];
    if (t == 0) g_cnt = 0;                     // reset point counter for next replay

    int p0 = t * 4;
    int b  = p0 / HW;
    int p  = p0 % HW;
    int i  = p / W;                            // W % 4 == 0 -> all 4 same row
    int j0 = p % W;
    float fi = (float)i;

    unsigned long long vs[4] = {va.x, va.y, vb.x, vb.y};
    float ox[4], oy[4];
    #pragma unroll
    for (int c = 0; c < 4; c++) {
        unsigned long long v = vs[c];
        float den = (float)(int)(v & 0x3FFFFFULL)          * (1.0f/4096.0f);
        float sy  = (float)(int)((v >> 22) & 0x1FFFFFULL)  * (1.0f/4096.0f);
        float sx  = (float)(int)(v >> 43)                  * (1.0f/2048.0f);
        float nx  = sx - 8.0f * den;
        float ny  = sy - 4.0f * den;
        float inv = 1.0f / (den + 1e-6f);
        ox[c] = (float)(j0 + c) + 0.6f * nx * inv;
        oy[c] = fi              + 0.6f * ny * inv;
    }
    *(float4*)(out + b*2*HW + p)      = make_float4(ox[0], ox[1], ox[2], ox[3]);
    *(float4*)(out + b*2*HW + HW + p) = make_float4(oy[0], oy[1], oy[2], oy[3]);
}

extern "C" void kernel_launch(void* const* d_in, const int* in_sizes, int n_in,
                              void* d_out, int out_size) {
    const float* src = (const float*)d_in[0];
    const float* dst = (const float*)d_in[1];
    const int* xx  = (const int*)d_in[2];
    const int* yy  = (const int*)d_in[3];
    int K = in_sizes[2];   // 105 search offsets
    int C = in_sizes[6];   // 441 sense offsets (21x21 grid, rebuilt row-major)
    float* out = (float*)d_out;

    compactK      <<<(B*HW)/(NT*2), NT>>>(src);
    searchScatterK<<<592, NT>>>(src, dst, xx, yy, K, C);
    finalB        <<<(B*HW)/(NT*4), NT>>>(out);
}

// round 12
// speedup vs baseline: 1.3208x; 1.0083x over previous
#include <cuda_runtime.h>
#include <math.h>

#define H 256
#define W 832
#define B 2
#define HW (H*W)
#define INFV 1e9f
#define NT 256
#define CAP 32768

// Packed fixed-point accumulator per pixel (cleared by compactK each replay;
// integer atomics -> bit-deterministic).
//   bits[ 0,22): sum w12                      (den,  w12 = round(w*2^12))
//   bits[22,43): sum w12*(dy+4)               (ny, weight-proportional bias)
//   bits[43,64): sum w11*(dx+8)               (nx,  w11 = round(w*2^11))
// Sparsify guarantees kept points pairwise Chebyshev dist >= 3 -> <= 49
// contributions per pixel -> no field overflow/carries.
__device__ ulonglong2 g_pack[(B*HW)/2];
__device__ int g_cnt;           // kept-point count (reset by finalB for next replay)
__device__ int g_kept[CAP];     // flat positions b*HW + p

// circular 3x3 box blur at (i,j)  (matches sum of jnp.roll wraps)
__device__ __forceinline__ float blur_at(const float* __restrict__ m, int i, int j) {
    float s = 0.f;
    #pragma unroll
    for (int di = -1; di <= 1; di++) {
        int ii = i + di; ii = (ii < 0) ? ii + H : (ii >= H ? ii - H : ii);
        #pragma unroll
        for (int dj = -1; dj <= 1; dj++) {
            int jj = j + dj; jj = (jj < 0) ? jj + W : (jj >= W ? jj - W : jj);
            s += m[ii*W + jj];
        }
    }
    return s;
}

// orientation = atan2(gy,gx) of blurred map, jnp.gradient border rules
__device__ __forceinline__ float theta_at(const float* __restrict__ m, int i, int j) {
    float gy, gx;
    if (i == 0)        gy = blur_at(m, 1, j)   - blur_at(m, 0, j);
    else if (i == H-1) gy = blur_at(m, H-1, j) - blur_at(m, H-2, j);
    else               gy = 0.5f * (blur_at(m, i+1, j) - blur_at(m, i-1, j));
    if (j == 0)        gx = blur_at(m, i, 1)   - blur_at(m, i, 0);
    else if (j == W-1) gx = blur_at(m, i, W-1) - blur_at(m, i, W-2);
    else               gx = 0.5f * (blur_at(m, i, j+1) - blur_at(m, i, j-1));
    return atan2f(gy, gx);
}

// ---- Kernel 1: thread-local sparsify + warp-shuffle compaction; clears g_pack ----
// A pixel is kept iff it is an edge and no edge with smaller linear index lies
// in its 5x5 window: rows i-2,i-1 (all 5 cols) and row i (2 cols left) only.
// No ballots on the load path, no block syncs; append via warp prefix-sum.
__global__ void __launch_bounds__(NT)
compactK(const float* __restrict__ src) {
    int t    = blockIdx.x * NT + threadIdx.x;   // one thread = 4 consecutive pixels
    int lane = threadIdx.x & 31;
    int base = t * 4;

    // clear this thread's 4 accumulators (two independent st.128)
    g_pack[2*t]     = make_ulonglong2(0ULL, 0ULL);
    g_pack[2*t + 1] = make_ulonglong2(0ULL, 0ULL);

    int b  = base / HW;
    int p0 = base % HW;
    const float* s = src + b*HW;
    float4 v = *(const float4*)(s + p0);        // coalesced; W % 4 == 0 -> same row

    bool e[4] = {v.x > 0.5f, v.y > 0.5f, v.z > 0.5f, v.w > 0.5f};
    int keepm = 0, kn = 0;
    if (e[0] | e[1] | e[2] | e[3]) {            // ~8% of threads
        int i = p0 / W, j0 = p0 % W;
        if (i >= 2 && j0 >= 2) {                // interior: unconditional loads (MLP)
            const float* r2 = s + (i-2)*W;
            const float* r1 = s + (i-1)*W;
            const float* r0 = s + i*W;
            #pragma unroll
            for (int c = 0; c < 4; c++) {
                if (!e[c]) continue;
                int j = j0 + c;
                float acc = r2[j-2] + r2[j-1] + r2[j] + r2[j+1] + r2[j+2]
                          + r1[j-2] + r1[j-1] + r1[j] + r1[j+1] + r1[j+2]
                          + r0[j-2] + r0[j-1];
                if (acc <= 0.5f) { keepm |= 1 << c; kn++; }
            }
        } else {                                 // border: bounds-checked
            #pragma unroll
            for (int c = 0; c < 4; c++) {
                if (!e[c]) continue;
                int j = j0 + c;
                bool viol = false;
                #pragma unroll
                for (int r = -2; r <= -1; r++) {
                    int row = i + r;
                    if (row < 0) continue;
                    const float* rp = s + row*W;
                    #pragma unroll
                    for (int dx = -2; dx <= 2; dx++) {
                        int jj = j + dx;
                        if (jj >= 0 && jj < W && rp[jj] > 0.5f) viol = true;
                    }
                }
                #pragma unroll
                for (int dx = -2; dx <= -1; dx++) {
                    int jj = j + dx;
                    if (jj >= 0 && s[i*W + jj] > 0.5f) viol = true;
                }
                if (!viol) { keepm |= 1 << c; kn++; }
            }
        }
    }

    // warp-aggregated append (prefix-sum over per-thread counts)
    unsigned act = __ballot_sync(0xffffffffu, kn > 0);
    if (!act) return;
    int pf = kn;
    #pragma unroll
    for (int o = 1; o < 32; o <<= 1) {
        int x = __shfl_up_sync(0xffffffffu, pf, o);
        if (lane >= o) pf += x;
    }
    int tot = __shfl_sync(0xffffffffu, pf, 31);
    int slot0 = 0;
    if (lane == 0) slot0 = atomicAdd(&g_cnt, tot);
    slot0 = __shfl_sync(0xffffffffu, slot0, 0);
    if (kn) {
        int slot = slot0 + pf - kn;
        #pragma unroll
        for (int c = 0; c < 4; c++)
            if (keepm & (1 << c)) {
                if (slot < CAP) g_kept[slot] = base + c;
                slot++;
            }
    }
}

// ---- Kernel 2: one warp per kept point: search + coalesced integer scatter ----
__global__ void __launch_bounds__(NT)
searchScatterK(const float* __restrict__ src, const float* __restrict__ dst,
               const int* __restrict__ xx,  const int* __restrict__ yy,  int K,
               int C) {
    __shared__ int4  s_tap[448];  // row-major taps: {ox, oy, w11, w12}
    __shared__ int   s_kco[128];  // search offsets packed (oy<<16)|(ox&0xffff)
    __shared__ float s_kd[128];   // search distances

    int tid = threadIdx.x;
    // Row-major 21x21 tap table (accumulation commutes -> tap order free;
    // row-major makes scatter lanes hit consecutive addresses -> coalesced REDG).
    for (int k = tid; k < C; k += NT) {
        int oy = k / 21 - 10;
        int ox = k % 21 - 10;
        float w = expf(-sqrtf((float)(ox*ox + oy*oy)) / 5.0f);
        s_tap[k] = make_int4(ox, oy, (int)rintf(w * 2048.0f), (int)rintf(w * 4096.0f));
    }
    for (int k = tid; k < K; k += NT) {
        int ox = xx[k], oy = yy[k];
        s_kco[k] = (oy << 16) | (ox & 0xffff);
        s_kd[k]  = sqrtf((float)(ox*ox + oy*oy));
    }
    __syncthreads();

    int gw    = (blockIdx.x * NT + tid) >> 5;
    int lane  = tid & 31;
    int nWarp = (gridDim.x * NT) >> 5;
    int n = g_cnt; if (n > CAP) n = CAP;

    for (int pt = gw; pt < n; pt += nWarp) {
        int pos = g_kept[pt];
        int b = pos / HW, p = pos % HW;
        int i = p / W,   j = p % W;
        const float* s = src + b*HW;
        const float* d = dst + b*HW;

        float ts = 0.f;
        if (lane == 0) ts = theta_at(s, i, j);
        ts = __shfl_sync(0xffffffffu, ts, 0);

        // search split across lanes (per-lane k strictly increasing; input
        // offset order preserved -> first-min == reference argmin)
        float best = INFV; int bestk = K;
        for (int k = lane; k < K; k += 32) {
            int co = s_kco[k];
            int ox = (int)(short)(co & 0xffff), oy = co >> 16;
            int ii = i + oy, jj = j + ox;
            if (ii >= 0 && ii < H && jj >= 0 && jj < W && d[ii*W + jj] > 0.5f) {
                float td = theta_at(d, ii, jj);
                float sc = 20.0f * s_kd[k] + 10.5f * (1.0f - cosf(ts - td));
                if (sc < best) { best = sc; bestk = k; }
            }
        }
        #pragma unroll
        for (int off = 16; off; off >>= 1) {   // argmin, first-index tie-break
            float s2 = __shfl_xor_sync(0xffffffffu, best,  off);
            int   k2 = __shfl_xor_sync(0xffffffffu, bestk, off);
            if (s2 < best || (s2 == best && k2 < bestk)) { best = s2; bestk = k2; }
        }
        if (best >= 0.5f * INFV) continue;

        int cow = s_kco[bestk];                // uniform broadcast read
        int idx8 = (int)(short)(cow & 0xffff) + 8;   // dx+8 in [1,15]
        int idy4 = (cow >> 16) + 4;                  // dy+4 in [1,7]

        // warp-parallel scatter (symmetric offsets: scatter == gather)
        unsigned long long* pk = (unsigned long long*)g_pack + b*HW;
        if (i >= 10 && i < H-10 && j >= 10 && j < W-10) {
            for (int k = lane; k < C; k += 32) {
                int4 tp = s_tap[k];
                unsigned long long add =
                    ((unsigned long long)(unsigned)(tp.z * idx8) << 43) |
                    ((unsigned long long)(unsigned)(tp.w * idy4) << 22) |
                    (unsigned long long)(unsigned)tp.w;
                atomicAdd(&pk[(i + tp.y)*W + (j + tp.x)], add);
            }
        } else {
            for (int k = lane; k < C; k += 32) {
                int4 tp = s_tap[k];
                int ii = i + tp.y, jj = j + tp.x;
                if (ii >= 0 && ii < H && jj >= 0 && jj < W) {
                    unsigned long long add =
                        ((unsigned long long)(unsigned)(tp.z * idx8) << 43) |
                        ((unsigned long long)(unsigned)(tp.w * idy4) << 22) |
                        (unsigned long long)(unsigned)tp.w;
                    atomicAdd(&pk[ii*W + jj], add);
                }
            }
        }
    }
}

// ---- Kernel 3: decode fixed-point (4 pixels/thread, 2 independent 16B loads) ----
__global__ void __launch_bounds__(NT)
finalB(float* __restrict__ out) {
    int t = blockIdx.x * NT + threadIdx.x;     // one thread = 4 consecutive pixels
    if (t >= (B*HW)/4) return;
    ulonglong2 va = g_pack[2*t];               // cleared by next replay's compactK
    ulonglong2 vb = g_pack[2*t + 1];
    if (t == 0) g_cnt = 0;                     // reset point counter for next replay

    int p0 = t * 4;
    int b  = p0 / HW;
    int p  = p0 % HW;
    int i  = p / W;                            // W % 4 == 0 -> all 4 same row
    int j0 = p % W;
    float fi = (float)i;

    unsigned long long vs[4] = {va.x, va.y, vb.x, vb.y};
    float ox[4], oy[4];
    #pragma unroll
    for (int c = 0; c < 4; c++) {
        unsigned long long v = vs[c];
        float den = (float)(int)(v & 0x3FFFFFULL)          * (1.0f/4096.0f);
        float sy  = (float)(int)((v >> 22) & 0x1FFFFFULL)  * (1.0f/4096.0f);
        float sx  = (float)(int)(v >> 43)                  * (1.0f/2048.0f);
        float nx  = sx - 8.0f * den;
        float ny  = sy - 4.0f * den;
        float inv = 1.0f / (den + 1e-6f);
        ox[c] = (float)(j0 + c) + 0.6f * nx * inv;
        oy[c] = fi              + 0.6f * ny * inv;
    }
    *(float4*)(out + b*2*HW + p)      = make_float4(ox[0], ox[1], ox[2], ox[3]);
    *(float4*)(out + b*2*HW + HW + p) = make_float4(oy[0], oy[1], oy[2], oy[3]);
}

extern "C" void kernel_launch(void* const* d_in, const int* in_sizes, int n_in,
                              void* d_out, int out_size) {
    const float* src = (const float*)d_in[0];
    const float* dst = (const float*)d_in[1];
    const int* xx  = (const int*)d_in[2];
    const int* yy  = (const int*)d_in[3];
    int K = in_sizes[2];   // 105 search offsets
    int C = in_sizes[6];   // 441 sense offsets (21x21 grid, rebuilt row-major)
    float* out = (float*)d_out;

    compactK      <<<(B*HW)/(NT*4), NT>>>(src);
    searchScatterK<<<592, NT>>>(src, dst, xx, yy, K, C);
    finalB        <<<(B*HW)/(NT*4), NT>>>(out);
}